// round 10
// baseline (speedup 1.0000x reference)
#include <cuda_runtime.h>
#include <cuda_fp16.h>
#include <math.h>
#include <stdint.h>

#define KC 19
#define MP 10
#define CH 720
#define CHP 768
#define JN 190
#define JP 192
#define NMAX 65536
#define TAU 6e-4f

// ---------------- scratch ----------------
__device__ __align__(256) __half g_Bh[JP * CHP];
__device__ __align__(256) float g_Bf[(size_t)JN * CH];
__device__ float g_mu[NMAX];
__device__ float g_P[NMAX];
__device__ float g_Q[NMAX];
__device__ float g_e[(size_t)NMAX * MP];
__device__ float g_c[NMAX];
__device__ float g_S[KC];
__device__ int   g_cnt[KC];
__device__ float g_T3[3][JN];
__device__ int      g_fixcnt;
__device__ int      g_fixn[NMAX];
__device__ unsigned g_fixmask[NMAX];

// ---------------- helpers ----------------
__device__ __forceinline__ uint32_t smem_u32(const void* p) {
    uint32_t a;
    asm("{ .reg .u64 t; cvta.to.shared.u64 t, %1; cvt.u32.u64 %0, t; }" : "=r"(a) : "l"(p));
    return a;
}
__device__ __forceinline__ float warpReduceSum(float v) {
    #pragma unroll
    for (int o = 16; o > 0; o >>= 1) v += __shfl_xor_sync(0xffffffffu, v, o);
    return v;
}
__device__ __forceinline__ float blockReduceSum(float v, float* sh) {
    __syncthreads();
    v = warpReduceSum(v);
    int lane = threadIdx.x & 31, w = threadIdx.x >> 5;
    if (lane == 0) sh[w] = v;
    __syncthreads();
    int nw = (blockDim.x + 31) >> 5;
    v = (threadIdx.x < nw) ? sh[threadIdx.x] : 0.f;
    if (w == 0) { v = warpReduceSum(v); if (lane == 0) sh[0] = v; }
    __syncthreads();
    return sh[0];
}
__device__ __forceinline__ void split2h(float a0, float a1, unsigned& h, unsigned& l) {
    __half2 hh = __floats2half2_rn(a0, a1);
    float2 hf = __half22float2(hh);
    __half2 ll = __floats2half2_rn(a0 - hf.x, a1 - hf.y);
    h = *(unsigned*)&hh;
    l = *(unsigned*)&ll;
}

#define LDMX4(r0, r1, r2, r3, addr) \
    asm volatile("ldmatrix.sync.aligned.m8n8.x4.shared.b16 {%0,%1,%2,%3}, [%4];" \
                 : "=r"(r0), "=r"(r1), "=r"(r2), "=r"(r3) : "r"(addr))

#define MMA16816H(d, a, b0, b1) \
    asm volatile("mma.sync.aligned.m16n8k16.row.col.f32.f16.f16.f32 " \
                 "{%0,%1,%2,%3}, {%4,%5,%6,%7}, {%8,%9}, {%0,%1,%2,%3};" \
                 : "+f"((d)[0]), "+f"((d)[1]), "+f"((d)[2]), "+f"((d)[3]) \
                 : "r"((a)[0]), "r"((a)[1]), "r"((a)[2]), "r"((a)[3]), "r"(b0), "r"(b1))

#define CP_ASYNC16(dst, src) \
    asm volatile("cp.async.ca.shared.global [%0], [%1], 16;" \
                 :: "r"(dst), "l"(src) : "memory")

// ---------------- K0: warp-per-row stats ----------------
__global__ __launch_bounds__(256) void kstats(const float* __restrict__ x,
                                              const float* __restrict__ gamma,
                                              const float* __restrict__ beta, int N) {
    int warp = threadIdx.x >> 5, lane = threadIdx.x & 31;
    int n = blockIdx.x * 8 + warp;
    if (n >= N) return;
    const float4* xr = (const float4*)(x + (size_t)n * CH);
    float4 v[6];
    float s = 0.f, sq = 0.f;
    #pragma unroll
    for (int i = 0; i < 6; i++) {
        int idx = i * 32 + lane;
        if (idx < 180) {
            v[i] = xr[idx];
            s += v[i].x + v[i].y + v[i].z + v[i].w;
            sq += v[i].x * v[i].x + v[i].y * v[i].y + v[i].z * v[i].z + v[i].w * v[i].w;
        } else v[i] = make_float4(0, 0, 0, 0);
    }
    s = warpReduceSum(s);
    sq = warpReduceSum(sq);
    float mu = s * (1.f / (float)CH);
    float rs = rsqrtf(sq * (1.f / (float)CH) - mu * mu + 1e-5f);
    float yn = 0.f;
    #pragma unroll
    for (int i = 0; i < 6; i++) {
        int idx = i * 32 + lane;
        if (idx < 180) {
            float4 g4 = ((const float4*)gamma)[idx];
            float4 b4 = ((const float4*)beta)[idx];
            float a = (v[i].x - mu) * rs * g4.x + b4.x;
            float b = (v[i].y - mu) * rs * g4.y + b4.y;
            float c = (v[i].z - mu) * rs * g4.z + b4.z;
            float d = (v[i].w - mu) * rs * g4.w + b4.w;
            yn += a * a + b * b + c * c + d * d;
        }
    }
    yn = warpReduceSum(yn);
    float inv = 1.f / fmaxf(sqrtf(yn), 1e-12f);
    if (lane == 0) { g_mu[n] = mu; g_P[n] = rs * inv; g_Q[n] = inv; }
}

// ---------------- K1: normalize prototypes (fp16 + fp32) + init ----------------
__global__ __launch_bounds__(192) void kprotoB(const float* __restrict__ proto) {
    int p = blockIdx.x;
    int t = threadIdx.x;
    __shared__ float sh[32];
    if (p == JN) {
        ((uint2*)(g_Bh + (size_t)190 * CHP))[t] = make_uint2(0u, 0u);
        ((uint2*)(g_Bh + (size_t)191 * CHP))[t] = make_uint2(0u, 0u);
        if (t < KC) { g_S[t] = 0.f; g_cnt[t] = 0; }
        if (t == 0) g_fixcnt = 0;
        for (int j = t; j < 3 * JN; j += 192) ((float*)g_T3)[j] = 0.f;
        return;
    }
    int k = p / MP, m = p % MP;
    int j = m * KC + k;
    const float4* pr = (const float4*)(proto + (size_t)p * CH);
    float4 v = make_float4(0, 0, 0, 0);
    float ss = 0.f;
    if (t < 180) {
        v = pr[t];
        ss = v.x * v.x + v.y * v.y + v.z * v.z + v.w * v.w;
    }
    ss = blockReduceSum(ss, sh);
    float inv = 1.f / fmaxf(sqrtf(ss), 1e-12f);
    uint2 h = make_uint2(0u, 0u);
    if (t < 180) {
        float4 f = make_float4(v.x * inv, v.y * inv, v.z * inv, v.w * inv);
        __half2 h0 = __floats2half2_rn(f.x, f.y);
        __half2 h1 = __floats2half2_rn(f.z, f.w);
        h.x = *(unsigned*)&h0;
        h.y = *(unsigned*)&h1;
        ((float4*)(g_Bf + (size_t)j * CH))[t] = f;
    }
    ((uint2*)(g_Bh + (size_t)j * CHP))[t] = h;
}

// ---------------- knull: filler so GEMM is launch #4 for ncu ----------------
__global__ void knull() {
    int t = threadIdx.x;
    for (int j = t; j < 3 * JN; j += 192) ((float*)g_T3)[j] = 0.f;
}

// ---------------- K2: HMMA fp16 GEMM 128x192, 8 warps, warp tile 32x96 ----------------
// Stage: Ahi 16K @0, Alo 16K @16384, B 24K @32768 -> 56K; 2 stages = 114688.
#define STG 57344
#define GEMM_SMEM (2 * STG)

__global__ __launch_bounds__(256, 1) void kgemm_mma(const float* __restrict__ x,
                                                    const float* __restrict__ gamma,
                                                    const float* __restrict__ beta,
                                                    float* __restrict__ sim, int N) {
    extern __shared__ char smem[];
    const uint32_t sb = smem_u32(smem);

    int tid = threadIdx.x;
    int lane = tid & 31, warp = tid >> 5;        // 8 warps
    int wm = warp & 3, wn = warp >> 2;           // 4 M-warps x 2 N-warps
    int rowBase = (int)blockIdx.x * 128;

    int arow = tid >> 4, aq = tid & 15;          // A: rows arow + r*16 (r<8), quad aq
    int brow = tid >> 3, bq = tid & 7;           // B: rows brow + r*32 (r<6), uint4 bq

    float mu[8], Pv[8], Qv[8];
    #pragma unroll
    for (int r = 0; r < 8; r++) {
        int gr = rowBase + arow + r * 16;
        if (gr < N) { mu[r] = g_mu[gr]; Pv[r] = g_P[gr]; Qv[r] = g_Q[gr]; }
        else        { mu[r] = 0.f; Pv[r] = 0.f; Qv[r] = 0.f; }
    }

    float acc[2][12][4];
    #pragma unroll
    for (int t = 0; t < 2; t++)
        #pragma unroll
        for (int nt = 0; nt < 12; nt++)
            #pragma unroll
            for (int i = 0; i < 4; i++) acc[t][nt][i] = 0.f;

    float4 xr[8], g4, b4;

    // prologue: prefetch chunk 0
    {
        g4 = ((const float4*)gamma)[aq];
        b4 = ((const float4*)beta)[aq];
        #pragma unroll
        for (int r = 0; r < 8; r++) {
            int gr = rowBase + arow + r * 16;
            xr[r] = (gr < N) ? ((const float4*)(x + (size_t)gr * CH))[aq]
                             : make_float4(0, 0, 0, 0);
        }
        uint32_t sB = sb + 32768;
        #pragma unroll
        for (int r = 0; r < 6; r++) {
            int row = brow + r * 32;
            uint32_t off = (uint32_t)(row * 128 + ((bq * 16) ^ ((row & 7) << 4)));
            CP_ASYNC16(sB + off, (const char*)(g_Bh + (size_t)row * CHP) + bq * 16);
        }
        asm volatile("cp.async.commit_group;" ::: "memory");
    }

    for (int c = 0; c < 12; c++) {
        uint32_t st = sb + (uint32_t)(c & 1) * STG;
        uint32_t sAhi = st, sAlo = st + 16384, sB = st + 32768;

        // convert + store A(c): fp16 hi/lo, 8 rows per thread
        #pragma unroll
        for (int r = 0; r < 8; r++) {
            float yx = (xr[r].x - mu[r]) * Pv[r] * g4.x + Qv[r] * b4.x;
            float yy = (xr[r].y - mu[r]) * Pv[r] * g4.y + Qv[r] * b4.y;
            float yz = (xr[r].z - mu[r]) * Pv[r] * g4.z + Qv[r] * b4.z;
            float yw = (xr[r].w - mu[r]) * Pv[r] * g4.w + Qv[r] * b4.w;
            unsigned h0, l0, h1, l1;
            split2h(yx, yy, h0, l0);
            split2h(yz, yw, h1, l1);
            int row = arow + r * 16;
            uint32_t off = (uint32_t)(row * 128 + ((aq * 8) ^ ((row & 7) << 4)));
            asm volatile("st.shared.v2.b32 [%0], {%1,%2};" :: "r"(sAhi + off), "r"(h0), "r"(h1));
            asm volatile("st.shared.v2.b32 [%0], {%1,%2};" :: "r"(sAlo + off), "r"(l0), "r"(l1));
        }
        asm volatile("cp.async.wait_group 0;" ::: "memory");
        __syncthreads();

        // prefetch chunk c+1
        if (c < 11) {
            int c0 = (c + 1) * 64;
            bool kin = (c0 + aq * 4) < CH;
            g4 = kin ? ((const float4*)gamma)[(c0 >> 2) + aq] : make_float4(0, 0, 0, 0);
            b4 = kin ? ((const float4*)beta)[(c0 >> 2) + aq]  : make_float4(0, 0, 0, 0);
            #pragma unroll
            for (int r = 0; r < 8; r++) {
                int gr = rowBase + arow + r * 16;
                xr[r] = (kin && gr < N) ? ((const float4*)(x + (size_t)gr * CH))[(c0 >> 2) + aq]
                                        : make_float4(0, 0, 0, 0);
            }
            uint32_t nB = sb + (uint32_t)((c + 1) & 1) * STG + 32768;
            #pragma unroll
            for (int r = 0; r < 6; r++) {
                int row = brow + r * 32;
                uint32_t off = (uint32_t)(row * 128 + ((bq * 16) ^ ((row & 7) << 4)));
                CP_ASYNC16(nB + off, (const char*)(g_Bh + (size_t)row * CHP + c0) + bq * 16);
            }
            asm volatile("cp.async.commit_group;" ::: "memory");
        }

        // MMA on stage c&1 — chunk 11: only s=0 has real K
        int smax = (c == 11) ? 1 : 4;
        #pragma unroll
        for (int s = 0; s < 4; s++) {
            if (s >= smax) break;
            uint32_t ahi[2][4], alo[2][4], bh[6][4];
            uint32_t kb = (uint32_t)(s * 32 + ((lane >> 4) & 1) * 16);
            #pragma unroll
            for (int t = 0; t < 2; t++) {
                int row = wm * 32 + t * 16 + (lane & 15);
                uint32_t off = (uint32_t)(row * 128) + (kb ^ ((uint32_t)(row & 7) << 4));
                LDMX4(ahi[t][0], ahi[t][1], ahi[t][2], ahi[t][3], sAhi + off);
                LDMX4(alo[t][0], alo[t][1], alo[t][2], alo[t][3], sAlo + off);
            }
            #pragma unroll
            for (int g = 0; g < 6; g++) {
                int row = wn * 96 + g * 16 + (lane & 15);
                uint32_t off = (uint32_t)(row * 128) + (kb ^ ((uint32_t)(row & 7) << 4));
                LDMX4(bh[g][0], bh[g][1], bh[g][2], bh[g][3], sB + off);
            }
            #pragma unroll
            for (int t = 0; t < 2; t++)
                #pragma unroll
                for (int g = 0; g < 6; g++)
                    #pragma unroll
                    for (int h = 0; h < 2; h++) {
                        int nt = g * 2 + h;
                        MMA16816H(acc[t][nt], ahi[t], bh[g][h], bh[g][h + 2]);
                        MMA16816H(acc[t][nt], alo[t], bh[g][h], bh[g][h + 2]);
                    }
        }
    }

    // epilogue
    #pragma unroll
    for (int t = 0; t < 2; t++) {
        int r0 = rowBase + wm * 32 + t * 16 + (lane >> 2);
        #pragma unroll
        for (int nt = 0; nt < 12; nt++) {
            int cc = wn * 96 + nt * 8 + ((lane & 3) << 1);
            if (cc < JN) {
                if (r0 < N)
                    *(float2*)(sim + (size_t)r0 * JN + cc) =
                        make_float2(acc[t][nt][0], acc[t][nt][1]);
                if (r0 + 8 < N)
                    *(float2*)(sim + (size_t)(r0 + 8) * JN + cc) =
                        make_float2(acc[t][nt][2], acc[t][nt][3]);
            }
        }
    }
}

// ---------------- K3: kpix + near-tie flagging ----------------
#define KPIX_SMEM (64 * JN * 4)
__global__ __launch_bounds__(128) void kpix(const float* __restrict__ sim,
                                            const int* __restrict__ gt,
                                            float* __restrict__ pred_out, int N) {
    extern __shared__ float srow[];
    __shared__ float sS[KC];
    __shared__ int sC[KC];
    if (threadIdx.x < KC) { sS[threadIdx.x] = 0.f; sC[threadIdx.x] = 0; }
    int base = blockIdx.x * 64;
    int npix = min(64, N - base);
    if (npix <= 0) return;
    int n4 = npix * JN / 2;
    const float2* src = (const float2*)(sim + (size_t)base * JN);
    float2* dst = (float2*)srow;
    for (int i = threadIdx.x; i < n4; i += 128) dst[i] = src[i];
    __syncthreads();
    if (threadIdx.x < npix) {
        int n = base + threadIdx.x;
        const float* row = srow + threadIdx.x * JN;
        int g = gt[n];
        float mk[KC];
        float best = -3.4e38f; int bk = 0;
        #pragma unroll
        for (int k = 0; k < KC; k++) {
            float m0 = row[k];
            #pragma unroll
            for (int m = 1; m < MP; m++) m0 = fmaxf(m0, row[m * KC + k]);
            mk[k] = m0;
            if (m0 > best) { best = m0; bk = k; }
        }
        pred_out[n] = (float)bk;
        unsigned mask = 0; int ccount = 0;
        float thr = best - TAU;
        #pragma unroll
        for (int k = 0; k < KC; k++)
            if (mk[k] > thr) { mask |= (1u << k); ccount++; }
        if (ccount > 1) {
            int idx = atomicAdd(&g_fixcnt, 1);
            g_fixn[idx] = n;
            g_fixmask[idx] = mask;
        }
        float se = 0.f;
        #pragma unroll
        for (int m = 0; m < MP; m++) {
            float e = expf(row[m * KC + g] * 20.0f);
            g_e[(size_t)n * MP + m] = e;
            se += e;
        }
        atomicAdd(&sS[g], se);
        atomicAdd(&sC[g], 1);
    }
    __syncthreads();
    if (threadIdx.x < KC) {
        if (sS[threadIdx.x] != 0.f) atomicAdd(&g_S[threadIdx.x], sS[threadIdx.x]);
        if (sC[threadIdx.x] != 0)   atomicAdd(&g_cnt[threadIdx.x], sC[threadIdx.x]);
    }
}

// ---------------- K4: exact fp32 argmax fixup ----------------
__global__ __launch_bounds__(256) void kfix(const float* __restrict__ x,
                                            const float* __restrict__ gamma,
                                            const float* __restrict__ beta,
                                            float* __restrict__ pred_out) {
    int lane = threadIdx.x & 31;
    int warp = (blockIdx.x * blockDim.x + threadIdx.x) >> 5;
    int nwarp = (gridDim.x * blockDim.x) >> 5;
    int cnt = g_fixcnt;
    for (int i = warp; i < cnt; i += nwarp) {
        int n = g_fixn[i];
        unsigned mask = g_fixmask[i];
        float mu = g_mu[n], P = g_P[n], Q = g_Q[n];
        const float4* xr = (const float4*)(x + (size_t)n * CH);
        float4 xn[6];
        #pragma unroll
        for (int q = 0; q < 6; q++) {
            int idx = q * 32 + lane;
            if (idx < 180) {
                float4 v = xr[idx];
                float4 g4 = ((const float4*)gamma)[idx];
                float4 b4 = ((const float4*)beta)[idx];
                xn[q].x = (v.x - mu) * P * g4.x + Q * b4.x;
                xn[q].y = (v.y - mu) * P * g4.y + Q * b4.y;
                xn[q].z = (v.z - mu) * P * g4.z + Q * b4.z;
                xn[q].w = (v.w - mu) * P * g4.w + Q * b4.w;
            } else xn[q] = make_float4(0, 0, 0, 0);
        }
        float best = -3.4e38f; int bk = 0;
        for (int k = 0; k < KC; k++) {
            if (!((mask >> k) & 1u)) continue;
            float smax = -3.4e38f;
            for (int m = 0; m < MP; m++) {
                const float4* pr = (const float4*)(g_Bf + (size_t)(m * KC + k) * CH);
                float d = 0.f;
                #pragma unroll
                for (int q = 0; q < 6; q++) {
                    int idx = q * 32 + lane;
                    if (idx < 180) {
                        float4 p = pr[idx];
                        d += xn[q].x * p.x + xn[q].y * p.y + xn[q].z * p.z + xn[q].w * p.w;
                    }
                }
                d = warpReduceSum(d);
                smax = fmaxf(smax, d);
            }
            if (smax > best) { best = smax; bk = k; }
        }
        if (lane == 0) pred_out[n] = (float)bk;
    }
}

// ---------------- tail ----------------
__global__ __launch_bounds__(256) void kT0(const int* __restrict__ gt, int N) {
    __shared__ float sT[JN];
    for (int j = threadIdx.x; j < JN; j += 256) sT[j] = 0.f;
    __syncthreads();
    int n = blockIdx.x * blockDim.x + threadIdx.x;
    if (n < N) {
        int g = gt[n];
        float c = 1.f / fmaxf(g_S[g], 1e-12f);
        g_c[n] = c;
        #pragma unroll
        for (int m = 0; m < MP; m++) atomicAdd(&sT[g * MP + m], c * g_e[(size_t)n * MP + m]);
    }
    __syncthreads();
    for (int j = threadIdx.x; j < JN; j += 256)
        if (sT[j] != 0.f) atomicAdd(&g_T3[0][j], sT[j]);
}

template<int IT>
__device__ __forceinline__ void r_chain(float* sr) {
    int t = threadIdx.x;
    if (t < JN) {
        float r = 1.f / (fmaxf(g_T3[0][t], 1e-12f) * (float)MP);
        #pragma unroll
        for (int it = 1; it < IT; it++)
            r = r / (fmaxf(r * g_T3[it][t], 1e-12f) * (float)MP);
        sr[t] = r;
    }
    __syncthreads();
}

template<int IT>
__global__ __launch_bounds__(256) void kCT(const int* __restrict__ gt, int N) {
    __shared__ float sr[JN];
    __shared__ float sT[JN];
    r_chain<IT>(sr);
    for (int j = threadIdx.x; j < JN; j += 256) sT[j] = 0.f;
    __syncthreads();
    int n = blockIdx.x * blockDim.x + threadIdx.x;
    if (n < N) {
        int g = gt[n];
        float cprev = g_c[n];
        float e[MP], V = 0.f;
        #pragma unroll
        for (int m = 0; m < MP; m++) { e[m] = g_e[(size_t)n * MP + m]; V += e[m] * sr[g * MP + m]; }
        float ns = fmaxf((float)g_cnt[g], 1.f);
        float c = cprev / (fmaxf(cprev * V, 1e-12f) * ns);
        g_c[n] = c;
        #pragma unroll
        for (int m = 0; m < MP; m++) atomicAdd(&sT[g * MP + m], c * e[m]);
    }
    __syncthreads();
    for (int j = threadIdx.x; j < JN; j += 256)
        if (sT[j] != 0.f) atomicAdd(&g_T3[IT][j], sT[j]);
}

// final: r3, c3, q full-column write (replaces memset + scatter)
__global__ __launch_bounds__(256) void kCQ(const int* __restrict__ gt,
                                           float* __restrict__ qout, int N) {
    __shared__ float sr[JN];
    r_chain<3>(sr);
    int n = blockIdx.x * blockDim.x + threadIdx.x;
    if (n >= N) return;
    int g = gt[n];
    float cprev = g_c[n];
    float e[MP], V = 0.f;
    #pragma unroll
    for (int m = 0; m < MP; m++) { e[m] = g_e[(size_t)n * MP + m]; V += e[m] * sr[g * MP + m]; }
    float ns = fmaxf((float)g_cnt[g], 1.f);
    float c = cprev / (fmaxf(cprev * V, 1e-12f) * ns);
    float cs = c * ns;
    float2 vals[MP / 2];
    #pragma unroll
    for (int m = 0; m < MP; m += 2)
        vals[m / 2] = make_float2(cs * e[m] * sr[g * MP + m],
                                  cs * e[m + 1] * sr[g * MP + m + 1]);
    const float2 z2 = make_float2(0.f, 0.f);
    #pragma unroll 1
    for (int k = 0; k < KC; k++) {
        float2* base = (float2*)(qout + ((size_t)k * N + n) * MP);
        if (k == g) {
            #pragma unroll
            for (int m2 = 0; m2 < MP / 2; m2++) base[m2] = vals[m2];
        } else {
            #pragma unroll
            for (int m2 = 0; m2 < MP / 2; m2++) base[m2] = z2;
        }
    }
}

// ---------------- launch ----------------
extern "C" void kernel_launch(void* const* d_in, const int* in_sizes, int n_in,
                              void* d_out, int out_size) {
    const float* x     = (const float*)d_in[0];
    const int*   gt    = (const int*)d_in[1];
    const float* gamma = (const float*)d_in[2];
    const float* beta  = (const float*)d_in[3];
    const float* proto = (const float*)d_in[4];
    int N = in_sizes[0] / CH;

    float* out  = (float*)d_out;
    float* sim  = out;
    float* q    = out + (size_t)N * JN;
    float* pred = out + 2 * (size_t)N * JN;

    cudaFuncSetAttribute(kgemm_mma, cudaFuncAttributeMaxDynamicSharedMemorySize, GEMM_SMEM);
    cudaFuncSetAttribute(kpix, cudaFuncAttributeMaxDynamicSharedMemorySize, KPIX_SMEM);

    kprotoB<<<JN + 1, 192>>>(proto);
    kstats<<<(N + 7) / 8, 256>>>(x, gamma, beta, N);
    knull<<<1, 192>>>();   // filler so kgemm is launch #4 (the one ncu captures)
    kgemm_mma<<<(N + 127) / 128, 256, GEMM_SMEM>>>(x, gamma, beta, sim, N);
    kpix<<<(N + 63) / 64, 128, KPIX_SMEM>>>(sim, gt, pred, N);
    kfix<<<256, 256>>>(x, gamma, beta, pred);

    kT0<<<(N + 255) / 256, 256>>>(gt, N);
    kCT<1><<<(N + 255) / 256, 256>>>(gt, N);
    kCT<2><<<(N + 255) / 256, 256>>>(gt, N);
    kCQ<<<(N + 255) / 256, 256>>>(gt, q, N);
}

// round 11
// speedup vs baseline: 1.0286x; 1.0286x over previous
#include <cuda_runtime.h>
#include <cuda_fp16.h>
#include <math.h>
#include <stdint.h>

#define KC 19
#define MP 10
#define CH 720
#define CHP 768
#define JN 190
#define JP 192
#define NMAX 65536
#define TAU 6e-4f

// ---------------- scratch ----------------
__device__ __align__(256) __half g_Bh[JP * CHP];
__device__ __align__(256) float g_Bf[(size_t)JN * CH];
__device__ float g_mu[NMAX];
__device__ float g_P[NMAX];
__device__ float g_Q[NMAX];
__device__ float g_e[(size_t)NMAX * MP];
__device__ float g_c[NMAX];
__device__ float g_S[KC];
__device__ int   g_cnt[KC];
__device__ float g_T3[3][JN];
__device__ int      g_fixcnt;
__device__ int      g_fixn[NMAX];
__device__ unsigned g_fixmask[NMAX];

// ---------------- helpers ----------------
__device__ __forceinline__ uint32_t smem_u32(const void* p) {
    uint32_t a;
    asm("{ .reg .u64 t; cvta.to.shared.u64 t, %1; cvt.u32.u64 %0, t; }" : "=r"(a) : "l"(p));
    return a;
}
__device__ __forceinline__ float warpReduceSum(float v) {
    #pragma unroll
    for (int o = 16; o > 0; o >>= 1) v += __shfl_xor_sync(0xffffffffu, v, o);
    return v;
}
__device__ __forceinline__ float blockReduceSum(float v, float* sh) {
    __syncthreads();
    v = warpReduceSum(v);
    int lane = threadIdx.x & 31, w = threadIdx.x >> 5;
    if (lane == 0) sh[w] = v;
    __syncthreads();
    int nw = (blockDim.x + 31) >> 5;
    v = (threadIdx.x < nw) ? sh[threadIdx.x] : 0.f;
    if (w == 0) { v = warpReduceSum(v); if (lane == 0) sh[0] = v; }
    __syncthreads();
    return sh[0];
}
__device__ __forceinline__ void split2h(float a0, float a1, unsigned& h, unsigned& l) {
    __half2 hh = __floats2half2_rn(a0, a1);
    float2 hf = __half22float2(hh);
    __half2 ll = __floats2half2_rn(a0 - hf.x, a1 - hf.y);
    h = *(unsigned*)&hh;
    l = *(unsigned*)&ll;
}

#define LDMX4(r0, r1, r2, r3, addr) \
    asm volatile("ldmatrix.sync.aligned.m8n8.x4.shared.b16 {%0,%1,%2,%3}, [%4];" \
                 : "=r"(r0), "=r"(r1), "=r"(r2), "=r"(r3) : "r"(addr))

#define MMA16816H(d, a, b0, b1) \
    asm volatile("mma.sync.aligned.m16n8k16.row.col.f32.f16.f16.f32 " \
                 "{%0,%1,%2,%3}, {%4,%5,%6,%7}, {%8,%9}, {%0,%1,%2,%3};" \
                 : "+f"((d)[0]), "+f"((d)[1]), "+f"((d)[2]), "+f"((d)[3]) \
                 : "r"((a)[0]), "r"((a)[1]), "r"((a)[2]), "r"((a)[3]), "r"(b0), "r"(b1))

#define CP_ASYNC16(dst, src) \
    asm volatile("cp.async.ca.shared.global [%0], [%1], 16;" \
                 :: "r"(dst), "l"(src) : "memory")

// ---------------- K0: warp-per-row stats ----------------
__global__ __launch_bounds__(256) void kstats(const float* __restrict__ x,
                                              const float* __restrict__ gamma,
                                              const float* __restrict__ beta, int N) {
    int warp = threadIdx.x >> 5, lane = threadIdx.x & 31;
    int n = blockIdx.x * 8 + warp;
    if (n >= N) return;
    const float4* xr = (const float4*)(x + (size_t)n * CH);
    float4 v[6];
    float s = 0.f, sq = 0.f;
    #pragma unroll
    for (int i = 0; i < 6; i++) {
        int idx = i * 32 + lane;
        if (idx < 180) {
            v[i] = xr[idx];
            s += v[i].x + v[i].y + v[i].z + v[i].w;
            sq += v[i].x * v[i].x + v[i].y * v[i].y + v[i].z * v[i].z + v[i].w * v[i].w;
        } else v[i] = make_float4(0, 0, 0, 0);
    }
    s = warpReduceSum(s);
    sq = warpReduceSum(sq);
    float mu = s * (1.f / (float)CH);
    float rs = rsqrtf(sq * (1.f / (float)CH) - mu * mu + 1e-5f);
    float yn = 0.f;
    #pragma unroll
    for (int i = 0; i < 6; i++) {
        int idx = i * 32 + lane;
        if (idx < 180) {
            float4 g4 = ((const float4*)gamma)[idx];
            float4 b4 = ((const float4*)beta)[idx];
            float a = (v[i].x - mu) * rs * g4.x + b4.x;
            float b = (v[i].y - mu) * rs * g4.y + b4.y;
            float c = (v[i].z - mu) * rs * g4.z + b4.z;
            float d = (v[i].w - mu) * rs * g4.w + b4.w;
            yn += a * a + b * b + c * c + d * d;
        }
    }
    yn = warpReduceSum(yn);
    float inv = 1.f / fmaxf(sqrtf(yn), 1e-12f);
    if (lane == 0) { g_mu[n] = mu; g_P[n] = rs * inv; g_Q[n] = inv; }
}

// ---------------- K1: normalize prototypes (fp16 + fp32) + init ----------------
__global__ __launch_bounds__(192) void kprotoB(const float* __restrict__ proto) {
    int p = blockIdx.x;
    int t = threadIdx.x;
    __shared__ float sh[32];
    if (p == JN) {
        ((uint2*)(g_Bh + (size_t)190 * CHP))[t] = make_uint2(0u, 0u);
        ((uint2*)(g_Bh + (size_t)191 * CHP))[t] = make_uint2(0u, 0u);
        if (t < KC) { g_S[t] = 0.f; g_cnt[t] = 0; }
        if (t == 0) g_fixcnt = 0;
        for (int j = t; j < 3 * JN; j += 192) ((float*)g_T3)[j] = 0.f;
        return;
    }
    int k = p / MP, m = p % MP;
    int j = m * KC + k;
    const float4* pr = (const float4*)(proto + (size_t)p * CH);
    float4 v = make_float4(0, 0, 0, 0);
    float ss = 0.f;
    if (t < 180) {
        v = pr[t];
        ss = v.x * v.x + v.y * v.y + v.z * v.z + v.w * v.w;
    }
    ss = blockReduceSum(ss, sh);
    float inv = 1.f / fmaxf(sqrtf(ss), 1e-12f);
    uint2 h = make_uint2(0u, 0u);
    if (t < 180) {
        float4 f = make_float4(v.x * inv, v.y * inv, v.z * inv, v.w * inv);
        __half2 h0 = __floats2half2_rn(f.x, f.y);
        __half2 h1 = __floats2half2_rn(f.z, f.w);
        h.x = *(unsigned*)&h0;
        h.y = *(unsigned*)&h1;
        ((float4*)(g_Bf + (size_t)j * CH))[t] = f;
    }
    ((uint2*)(g_Bh + (size_t)j * CHP))[t] = h;
}

// ---------------- knull: filler so GEMM is launch #4 for ncu ----------------
__global__ void knull() {
    int t = threadIdx.x;
    for (int j = t; j < 3 * JN; j += 192) ((float*)g_T3)[j] = 0.f;
}

// ---------------- K2: HMMA fp16 GEMM 128x192, convert in MMA shadow ----------------
// Stage: Ahi 16K @0, Alo 16K @16384, B 24K @32768 -> 56K; 2 stages.
#define STG 57344
#define GEMM_SMEM (2 * STG)

__global__ __launch_bounds__(256, 1) void kgemm_mma(const float* __restrict__ x,
                                                    const float* __restrict__ gamma,
                                                    const float* __restrict__ beta,
                                                    float* __restrict__ sim, int N) {
    extern __shared__ char smem[];
    const uint32_t sb = smem_u32(smem);

    int tid = threadIdx.x;
    int lane = tid & 31, warp = tid >> 5;        // 8 warps
    int wm = warp & 3, wn = warp >> 2;           // 4 M x 2 N
    int rowBase = (int)blockIdx.x * 128;

    int arow = tid >> 4, aq = tid & 15;          // A: rows arow + r*16 (r<8)
    int brow = tid >> 3, bq = tid & 7;           // B: rows brow + r*32 (r<6)

    float mu[8], Pv[8], Qv[8];
    #pragma unroll
    for (int r = 0; r < 8; r++) {
        int gr = rowBase + arow + r * 16;
        if (gr < N) { mu[r] = g_mu[gr]; Pv[r] = g_P[gr]; Qv[r] = g_Q[gr]; }
        else        { mu[r] = 0.f; Pv[r] = 0.f; Qv[r] = 0.f; }
    }

    float acc[2][12][4];
    #pragma unroll
    for (int t = 0; t < 2; t++)
        #pragma unroll
        for (int nt = 0; nt < 12; nt++)
            #pragma unroll
            for (int i = 0; i < 4; i++) acc[t][nt][i] = 0.f;

    float4 xr[8], g4, b4;

    // per-s MMA step on a given stage
    auto mma_step = [&](int s, uint32_t sAhi, uint32_t sAlo, uint32_t sB) {
        uint32_t ahi[2][4], alo[2][4], bh[6][4];
        uint32_t kb = (uint32_t)(s * 32 + ((lane >> 4) & 1) * 16);
        #pragma unroll
        for (int t = 0; t < 2; t++) {
            int row = wm * 32 + t * 16 + (lane & 15);
            uint32_t off = (uint32_t)(row * 128) + (kb ^ ((uint32_t)(row & 7) << 4));
            LDMX4(ahi[t][0], ahi[t][1], ahi[t][2], ahi[t][3], sAhi + off);
            LDMX4(alo[t][0], alo[t][1], alo[t][2], alo[t][3], sAlo + off);
        }
        #pragma unroll
        for (int g = 0; g < 6; g++) {
            int row = wn * 96 + g * 16 + (lane & 15);
            uint32_t off = (uint32_t)(row * 128) + (kb ^ ((uint32_t)(row & 7) << 4));
            LDMX4(bh[g][0], bh[g][1], bh[g][2], bh[g][3], sB + off);
        }
        #pragma unroll
        for (int t = 0; t < 2; t++)
            #pragma unroll
            for (int g = 0; g < 6; g++)
                #pragma unroll
                for (int h = 0; h < 2; h++) {
                    int nt = g * 2 + h;
                    MMA16816H(acc[t][nt], ahi[t], bh[g][h], bh[g][h + 2]);
                    MMA16816H(acc[t][nt], alo[t], bh[g][h], bh[g][h + 2]);
                }
    };

    // ======== prologue ========
    {
        // cp B(0) -> stage0
        uint32_t sB = sb + 32768;
        #pragma unroll
        for (int r = 0; r < 6; r++) {
            int row = brow + r * 32;
            uint32_t off = (uint32_t)(row * 128 + ((bq * 16) ^ ((row & 7) << 4)));
            CP_ASYNC16(sB + off, (const char*)(g_Bh + (size_t)row * CHP) + bq * 16);
        }
        asm volatile("cp.async.commit_group;" ::: "memory");

        // load + convert + store A(0) -> stage0
        g4 = ((const float4*)gamma)[aq];
        b4 = ((const float4*)beta)[aq];
        #pragma unroll
        for (int r = 0; r < 8; r++) {
            int gr = rowBase + arow + r * 16;
            xr[r] = (gr < N) ? ((const float4*)(x + (size_t)gr * CH))[aq]
                             : make_float4(0, 0, 0, 0);
        }
        #pragma unroll
        for (int r = 0; r < 8; r++) {
            float yx = (xr[r].x - mu[r]) * Pv[r] * g4.x + Qv[r] * b4.x;
            float yy = (xr[r].y - mu[r]) * Pv[r] * g4.y + Qv[r] * b4.y;
            float yz = (xr[r].z - mu[r]) * Pv[r] * g4.z + Qv[r] * b4.z;
            float yw = (xr[r].w - mu[r]) * Pv[r] * g4.w + Qv[r] * b4.w;
            unsigned h0, l0, h1, l1;
            split2h(yx, yy, h0, l0);
            split2h(yz, yw, h1, l1);
            int row = arow + r * 16;
            uint32_t off = (uint32_t)(row * 128 + ((aq * 8) ^ ((row & 7) << 4)));
            asm volatile("st.shared.v2.b32 [%0], {%1,%2};" :: "r"(sb + off), "r"(h0), "r"(h1));
            asm volatile("st.shared.v2.b32 [%0], {%1,%2};" :: "r"(sb + 16384 + off), "r"(l0), "r"(l1));
        }

        // cp B(1) -> stage1
        uint32_t nB = sb + STG + 32768;
        #pragma unroll
        for (int r = 0; r < 6; r++) {
            int row = brow + r * 32;
            uint32_t off = (uint32_t)(row * 128 + ((bq * 16) ^ ((row & 7) << 4)));
            CP_ASYNC16(nB + off, (const char*)(g_Bh + (size_t)row * CHP + 64) + bq * 16);
        }
        asm volatile("cp.async.commit_group;" ::: "memory");

        // load xr(1), g/b(1)
        g4 = ((const float4*)gamma)[16 + aq];
        b4 = ((const float4*)beta)[16 + aq];
        #pragma unroll
        for (int r = 0; r < 8; r++) {
            int gr = rowBase + arow + r * 16;
            xr[r] = (gr < N) ? ((const float4*)(x + (size_t)gr * CH))[16 + aq]
                             : make_float4(0, 0, 0, 0);
        }

        asm volatile("cp.async.wait_group 1;" ::: "memory");   // B(0) resident
        __syncthreads();
    }

    // ======== main loop: B(c) + A(c) resident; xr/g4/b4 hold (c+1); B(c+1) in flight ========
    for (int c = 0; c < 12; c++) {
        uint32_t st = sb + (uint32_t)(c & 1) * STG;
        uint32_t sAhi = st, sAlo = st + 16384, sB = st + 32768;

        mma_step(0, sAhi, sAlo, sB);

        // convert+store A(c+1) in the MMA shadow (stage (c+1)&1's A was freed pre-barrier)
        if (c < 11) {
            uint32_t st2 = sb + (uint32_t)((c + 1) & 1) * STG;
            #pragma unroll
            for (int r = 0; r < 8; r++) {
                float yx = (xr[r].x - mu[r]) * Pv[r] * g4.x + Qv[r] * b4.x;
                float yy = (xr[r].y - mu[r]) * Pv[r] * g4.y + Qv[r] * b4.y;
                float yz = (xr[r].z - mu[r]) * Pv[r] * g4.z + Qv[r] * b4.z;
                float yw = (xr[r].w - mu[r]) * Pv[r] * g4.w + Qv[r] * b4.w;
                unsigned h0, l0, h1, l1;
                split2h(yx, yy, h0, l0);
                split2h(yz, yw, h1, l1);
                int row = arow + r * 16;
                uint32_t off = (uint32_t)(row * 128 + ((aq * 8) ^ ((row & 7) << 4)));
                asm volatile("st.shared.v2.b32 [%0], {%1,%2};" :: "r"(st2 + off), "r"(h0), "r"(h1));
                asm volatile("st.shared.v2.b32 [%0], {%1,%2};" :: "r"(st2 + 16384 + off), "r"(l0), "r"(l1));
            }
            // prefetch xr(c+2) (global latency hidden under remaining MMAs)
            if (c < 10) {
                int c0 = (c + 2) * 64;
                bool kin = (c0 + aq * 4) < CH;
                g4 = kin ? ((const float4*)gamma)[(c0 >> 2) + aq] : make_float4(0, 0, 0, 0);
                b4 = kin ? ((const float4*)beta)[(c0 >> 2) + aq]  : make_float4(0, 0, 0, 0);
                #pragma unroll
                for (int r = 0; r < 8; r++) {
                    int gr = rowBase + arow + r * 16;
                    xr[r] = (kin && gr < N) ? ((const float4*)(x + (size_t)gr * CH))[(c0 >> 2) + aq]
                                            : make_float4(0, 0, 0, 0);
                }
            }
        }

        if (c != 11) {   // chunk 11 has only s=0 of real K
            mma_step(1, sAhi, sAlo, sB);
            mma_step(2, sAhi, sAlo, sB);
            mma_step(3, sAhi, sAlo, sB);
        }

        if (c < 11) asm volatile("cp.async.wait_group 0;" ::: "memory");  // B(c+1) resident
        __syncthreads();

        // cp B(c+2) into stage c&1 (safe: all warps past MMA(c))
        if (c < 10) {
            int c0 = (c + 2) * 64;
            uint32_t nB = sb + (uint32_t)(c & 1) * STG + 32768;
            #pragma unroll
            for (int r = 0; r < 6; r++) {
                int row = brow + r * 32;
                uint32_t off = (uint32_t)(row * 128 + ((bq * 16) ^ ((row & 7) << 4)));
                CP_ASYNC16(nB + off, (const char*)(g_Bh + (size_t)row * CHP + c0) + bq * 16);
            }
            asm volatile("cp.async.commit_group;" ::: "memory");
        }
    }

    // ======== epilogue ========
    #pragma unroll
    for (int t = 0; t < 2; t++) {
        int r0 = rowBase + wm * 32 + t * 16 + (lane >> 2);
        #pragma unroll
        for (int nt = 0; nt < 12; nt++) {
            int cc = wn * 96 + nt * 8 + ((lane & 3) << 1);
            if (cc < JN) {
                if (r0 < N)
                    *(float2*)(sim + (size_t)r0 * JN + cc) =
                        make_float2(acc[t][nt][0], acc[t][nt][1]);
                if (r0 + 8 < N)
                    *(float2*)(sim + (size_t)(r0 + 8) * JN + cc) =
                        make_float2(acc[t][nt][2], acc[t][nt][3]);
            }
        }
    }
}

// ---------------- K3: kpix + near-tie flagging ----------------
#define KPIX_SMEM (64 * JN * 4)
__global__ __launch_bounds__(128) void kpix(const float* __restrict__ sim,
                                            const int* __restrict__ gt,
                                            float* __restrict__ pred_out, int N) {
    extern __shared__ float srow[];
    __shared__ float sS[KC];
    __shared__ int sC[KC];
    if (threadIdx.x < KC) { sS[threadIdx.x] = 0.f; sC[threadIdx.x] = 0; }
    int base = blockIdx.x * 64;
    int npix = min(64, N - base);
    if (npix <= 0) return;
    int n4 = npix * JN / 2;
    const float2* src = (const float2*)(sim + (size_t)base * JN);
    float2* dst = (float2*)srow;
    for (int i = threadIdx.x; i < n4; i += 128) dst[i] = src[i];
    __syncthreads();
    if (threadIdx.x < npix) {
        int n = base + threadIdx.x;
        const float* row = srow + threadIdx.x * JN;
        int g = gt[n];
        float mk[KC];
        float best = -3.4e38f; int bk = 0;
        #pragma unroll
        for (int k = 0; k < KC; k++) {
            float m0 = row[k];
            #pragma unroll
            for (int m = 1; m < MP; m++) m0 = fmaxf(m0, row[m * KC + k]);
            mk[k] = m0;
            if (m0 > best) { best = m0; bk = k; }
        }
        pred_out[n] = (float)bk;
        unsigned mask = 0; int ccount = 0;
        float thr = best - TAU;
        #pragma unroll
        for (int k = 0; k < KC; k++)
            if (mk[k] > thr) { mask |= (1u << k); ccount++; }
        if (ccount > 1) {
            int idx = atomicAdd(&g_fixcnt, 1);
            g_fixn[idx] = n;
            g_fixmask[idx] = mask;
        }
        float se = 0.f;
        #pragma unroll
        for (int m = 0; m < MP; m++) {
            float e = expf(row[m * KC + g] * 20.0f);
            g_e[(size_t)n * MP + m] = e;
            se += e;
        }
        atomicAdd(&sS[g], se);
        atomicAdd(&sC[g], 1);
    }
    __syncthreads();
    if (threadIdx.x < KC) {
        if (sS[threadIdx.x] != 0.f) atomicAdd(&g_S[threadIdx.x], sS[threadIdx.x]);
        if (sC[threadIdx.x] != 0)   atomicAdd(&g_cnt[threadIdx.x], sC[threadIdx.x]);
    }
}

// ---------------- K4: exact fp32 argmax fixup ----------------
__global__ __launch_bounds__(256) void kfix(const float* __restrict__ x,
                                            const float* __restrict__ gamma,
                                            const float* __restrict__ beta,
                                            float* __restrict__ pred_out) {
    int lane = threadIdx.x & 31;
    int warp = (blockIdx.x * blockDim.x + threadIdx.x) >> 5;
    int nwarp = (gridDim.x * blockDim.x) >> 5;
    int cnt = g_fixcnt;
    for (int i = warp; i < cnt; i += nwarp) {
        int n = g_fixn[i];
        unsigned mask = g_fixmask[i];
        float mu = g_mu[n], P = g_P[n], Q = g_Q[n];
        const float4* xr = (const float4*)(x + (size_t)n * CH);
        float4 xn[6];
        #pragma unroll
        for (int q = 0; q < 6; q++) {
            int idx = q * 32 + lane;
            if (idx < 180) {
                float4 v = xr[idx];
                float4 g4 = ((const float4*)gamma)[idx];
                float4 b4 = ((const float4*)beta)[idx];
                xn[q].x = (v.x - mu) * P * g4.x + Q * b4.x;
                xn[q].y = (v.y - mu) * P * g4.y + Q * b4.y;
                xn[q].z = (v.z - mu) * P * g4.z + Q * b4.z;
                xn[q].w = (v.w - mu) * P * g4.w + Q * b4.w;
            } else xn[q] = make_float4(0, 0, 0, 0);
        }
        float best = -3.4e38f; int bk = 0;
        for (int k = 0; k < KC; k++) {
            if (!((mask >> k) & 1u)) continue;
            float smax = -3.4e38f;
            for (int m = 0; m < MP; m++) {
                const float4* pr = (const float4*)(g_Bf + (size_t)(m * KC + k) * CH);
                float d = 0.f;
                #pragma unroll
                for (int q = 0; q < 6; q++) {
                    int idx = q * 32 + lane;
                    if (idx < 180) {
                        float4 p = pr[idx];
                        d += xn[q].x * p.x + xn[q].y * p.y + xn[q].z * p.z + xn[q].w * p.w;
                    }
                }
                d = warpReduceSum(d);
                smax = fmaxf(smax, d);
            }
            if (smax > best) { best = smax; bk = k; }
        }
        if (lane == 0) pred_out[n] = (float)bk;
    }
}

// ---------------- tail ----------------
__global__ __launch_bounds__(256) void kT0(const int* __restrict__ gt, int N) {
    __shared__ float sT[JN];
    for (int j = threadIdx.x; j < JN; j += 256) sT[j] = 0.f;
    __syncthreads();
    int n = blockIdx.x * blockDim.x + threadIdx.x;
    if (n < N) {
        int g = gt[n];
        float c = 1.f / fmaxf(g_S[g], 1e-12f);
        g_c[n] = c;
        #pragma unroll
        for (int m = 0; m < MP; m++) atomicAdd(&sT[g * MP + m], c * g_e[(size_t)n * MP + m]);
    }
    __syncthreads();
    for (int j = threadIdx.x; j < JN; j += 256)
        if (sT[j] != 0.f) atomicAdd(&g_T3[0][j], sT[j]);
}

template<int IT>
__device__ __forceinline__ void r_chain(float* sr) {
    int t = threadIdx.x;
    if (t < JN) {
        float r = 1.f / (fmaxf(g_T3[0][t], 1e-12f) * (float)MP);
        #pragma unroll
        for (int it = 1; it < IT; it++)
            r = r / (fmaxf(r * g_T3[it][t], 1e-12f) * (float)MP);
        sr[t] = r;
    }
    __syncthreads();
}

template<int IT>
__global__ __launch_bounds__(256) void kCT(const int* __restrict__ gt, int N) {
    __shared__ float sr[JN];
    __shared__ float sT[JN];
    r_chain<IT>(sr);
    for (int j = threadIdx.x; j < JN; j += 256) sT[j] = 0.f;
    __syncthreads();
    int n = blockIdx.x * blockDim.x + threadIdx.x;
    if (n < N) {
        int g = gt[n];
        float cprev = g_c[n];
        float e[MP], V = 0.f;
        #pragma unroll
        for (int m = 0; m < MP; m++) { e[m] = g_e[(size_t)n * MP + m]; V += e[m] * sr[g * MP + m]; }
        float ns = fmaxf((float)g_cnt[g], 1.f);
        float c = cprev / (fmaxf(cprev * V, 1e-12f) * ns);
        g_c[n] = c;
        #pragma unroll
        for (int m = 0; m < MP; m++) atomicAdd(&sT[g * MP + m], c * e[m]);
    }
    __syncthreads();
    for (int j = threadIdx.x; j < JN; j += 256)
        if (sT[j] != 0.f) atomicAdd(&g_T3[IT][j], sT[j]);
}

// final: r3, c3, q scatter (memset'd beforehand)
__global__ __launch_bounds__(256) void kCQ(const int* __restrict__ gt,
                                           float* __restrict__ qout, int N) {
    __shared__ float sr[JN];
    r_chain<3>(sr);
    int n = blockIdx.x * blockDim.x + threadIdx.x;
    if (n >= N) return;
    int g = gt[n];
    float cprev = g_c[n];
    float e[MP], V = 0.f;
    #pragma unroll
    for (int m = 0; m < MP; m++) { e[m] = g_e[(size_t)n * MP + m]; V += e[m] * sr[g * MP + m]; }
    float ns = fmaxf((float)g_cnt[g], 1.f);
    float c = cprev / (fmaxf(cprev * V, 1e-12f) * ns);
    float cs = c * ns;
    size_t base = ((size_t)g * N + n) * MP;
    #pragma unroll
    for (int m = 0; m < MP; m++)
        qout[base + m] = cs * e[m] * sr[g * MP + m];
}

// ---------------- launch ----------------
extern "C" void kernel_launch(void* const* d_in, const int* in_sizes, int n_in,
                              void* d_out, int out_size) {
    const float* x     = (const float*)d_in[0];
    const int*   gt    = (const int*)d_in[1];
    const float* gamma = (const float*)d_in[2];
    const float* beta  = (const float*)d_in[3];
    const float* proto = (const float*)d_in[4];
    int N = in_sizes[0] / CH;

    float* out  = (float*)d_out;
    float* sim  = out;
    float* q    = out + (size_t)N * JN;
    float* pred = out + 2 * (size_t)N * JN;

    cudaFuncSetAttribute(kgemm_mma, cudaFuncAttributeMaxDynamicSharedMemorySize, GEMM_SMEM);
    cudaFuncSetAttribute(kpix, cudaFuncAttributeMaxDynamicSharedMemorySize, KPIX_SMEM);

    kprotoB<<<JN + 1, 192>>>(proto);
    kstats<<<(N + 7) / 8, 256>>>(x, gamma, beta, N);
    knull<<<1, 192>>>();   // filler so kgemm is launch #4 (the one ncu captures)
    kgemm_mma<<<(N + 127) / 128, 256, GEMM_SMEM>>>(x, gamma, beta, sim, N);
    kpix<<<(N + 63) / 64, 128, KPIX_SMEM>>>(sim, gt, pred, N);
    kfix<<<256, 256>>>(x, gamma, beta, pred);

    kT0<<<(N + 255) / 256, 256>>>(gt, N);
    kCT<1><<<(N + 255) / 256, 256>>>(gt, N);
    kCT<2><<<(N + 255) / 256, 256>>>(gt, N);
    cudaMemsetAsync(q, 0, (size_t)N * JN * sizeof(float));
    kCQ<<<(N + 255) / 256, 256>>>(gt, q, N);
}